// round 6
// baseline (speedup 1.0000x reference)
#include <cuda_runtime.h>
#include <cstdint>
#include <math.h>

// tril(A @ B), A,B lower-triangular fp32, N=4096.
// bf16 3-split GEMM on mma.sync.m16n8k16 (tcgen05/TMA unavailable on the
// harness's sm_103 (no 'a') PTX target).
//
// R6: 128x64 C tile, 128 threads (4 warps), warp tile 64x32 (loads/MMA=0.25),
// 3 CTAs/SM (regs<=170, smem 57.3KB/CTA). Load+convert of the next chunk is
// placed AFTER compute so staging regs don't overlap fragment live ranges;
// cross-CTA overlap hides the LDG tail. v4 shared stores halve STS wavefronts.

#define NDIM 4096
#define NB   32
#define BK   32
#define THREADS 128

#define A_ROWB 80              // 32 bf16 = 64B padded to 80B (conflict-free ldm)
#define ST_AH 0                // 128*80 = 10240
#define ST_AL 10240
#define ST_BH 20480            // 32 k-rows * 128B = 4096
#define ST_BL 24576
#define STAGE 28672
#define SMEM_DYN (2 * STAGE)   // 57344/CTA; x3 CTAs = 172KB < 228KB

static __device__ __forceinline__ uint32_t smem_u32(const void* p) {
    uint32_t a;
    asm("{ .reg .u64 t; cvta.to.shared.u64 t, %1; cvt.u32.u64 %0, t; }"
        : "=r"(a) : "l"(p));
    return a;
}

// pack two fp32 -> bf16x2, 'lo' in bits[15:0], 'hi' in bits[31:16]
static __device__ __forceinline__ uint32_t bf2(float lo, float hi) {
    uint32_t r;
    asm("cvt.rn.bf16x2.f32 %0, %1, %2;" : "=r"(r) : "f"(hi), "f"(lo));
    return r;
}

static __device__ __forceinline__ void ldm4(uint32_t d[4], uint32_t addr) {
    asm volatile("ldmatrix.sync.aligned.m8n8.x4.shared.b16 {%0,%1,%2,%3}, [%4];"
                 : "=r"(d[0]), "=r"(d[1]), "=r"(d[2]), "=r"(d[3]) : "r"(addr));
}
static __device__ __forceinline__ void ldm4t(uint32_t d[4], uint32_t addr) {
    asm volatile("ldmatrix.sync.aligned.m8n8.x4.trans.shared.b16 {%0,%1,%2,%3}, [%4];"
                 : "=r"(d[0]), "=r"(d[1]), "=r"(d[2]), "=r"(d[3]) : "r"(addr));
}

static __device__ __forceinline__ void mma16816(float* c, const uint32_t* a,
                                                const uint32_t* b) {
    asm volatile(
        "mma.sync.aligned.m16n8k16.row.col.f32.bf16.bf16.f32 "
        "{%0,%1,%2,%3}, {%4,%5,%6,%7}, {%8,%9}, {%0,%1,%2,%3};"
        : "+f"(c[0]), "+f"(c[1]), "+f"(c[2]), "+f"(c[3])
        : "r"(a[0]), "r"(a[1]), "r"(a[2]), "r"(a[3]), "r"(b[0]), "r"(b[1]));
}

static __device__ __forceinline__ void split4(float4 v, uint32_t& h01, uint32_t& h23,
                                              uint32_t& l01, uint32_t& l23) {
    h01 = bf2(v.x, v.y);
    h23 = bf2(v.z, v.w);
    float r0 = v.x - __uint_as_float(h01 << 16);
    float r1 = v.y - __uint_as_float(h01 & 0xFFFF0000u);
    float r2 = v.z - __uint_as_float(h23 << 16);
    float r3 = v.w - __uint_as_float(h23 & 0xFFFF0000u);
    l01 = bf2(r0, r1);
    l23 = bf2(r2, r3);
}

static __device__ __forceinline__ void sts4(uint32_t addr, uint32_t a, uint32_t b,
                                            uint32_t c, uint32_t d) {
    asm volatile("st.shared.v4.b32 [%0], {%1,%2,%3,%4};"
                 :: "r"(addr), "r"(a), "r"(b), "r"(c), "r"(d) : "memory");
}

__global__ __launch_bounds__(THREADS, 3)
void trimm_mma(const float* __restrict__ A, const float* __restrict__ B,
               float* __restrict__ C)
{
    extern __shared__ __align__(128) char dyn_smem[];
    const uint32_t sbase = smem_u32(dyn_smem);

    const int tid  = threadIdx.x;
    const int wid  = tid >> 5;
    const int lane = tid & 31;

    // ---- block id -> (bi,bj,half), largest-K first ----
    const int bid  = blockIdx.x;
    const int t    = bid >> 1;
    const int half = bid & 1;
    int g = (int)((sqrtf(8.0f * (float)t + 1.0f) - 1.0f) * 0.5f);
    while ((g + 1) * (g + 2) / 2 <= t) ++g;
    while (g * (g + 1) / 2 > t) --g;
    const int bj = t - g * (g + 1) / 2;
    const int bi = bj + (NB - 1) - g;
    const int bm0 = bi * 128;
    const int bn0 = bj * 128 + half * 64;
    const int kStart = bn0;
    const int kEnd   = bm0 + 128;
    const int nchunks = (kEnd - kStart) >> 5;   // 2..128

    // warp grid 2(m) x 2(n): warp tile 64x32
    const int m0w = (wid & 1) * 64;
    const int n0w = (wid >> 1) * 32;

    // ldmatrix lane addressing
    const uint32_t laneA    = (uint32_t)((lane & 15) * A_ROWB + ((lane >> 4) << 4));
    const uint32_t laneBRow = (uint32_t)((lane & 15) * 128);
    const uint32_t laneBCol = (uint32_t)((((lane >> 4) ^ (lane & 7)) << 4));

    // global load indices (128 threads)
    const int aRow = tid >> 2;            // 0..31 (+32 per pass, 4 passes)
    const int aK8  = (tid & 3) * 8;       // k float offset (8 floats/thread)
    const int bK   = tid >> 3;            // 0..15 (+16 per pass, 2 passes)
    const int bN8  = (tid & 7) * 8;       // n float offset (8 floats/thread)

    float acc[4][4][4];
#pragma unroll
    for (int mt = 0; mt < 4; ++mt)
#pragma unroll
        for (int nt = 0; nt < 4; ++nt)
#pragma unroll
            for (int e = 0; e < 4; ++e) acc[mt][nt][e] = 0.0f;

#define PRODUCE_CHUNK(k0, sbuf)                                                 \
    {                                                                           \
        _Pragma("unroll")                                                       \
        for (int p = 0; p < 4; ++p) {                                           \
            const float* ap = A + (size_t)(bm0 + aRow + p * 32) * NDIM          \
                                + (k0) + aK8;                                   \
            float4 v0 = *(const float4*)ap;                                     \
            float4 v1 = *(const float4*)(ap + 4);                               \
            uint32_t h01, h23, l01, l23, h45, h67, l45, l67;                    \
            split4(v0, h01, h23, l01, l23);                                     \
            split4(v1, h45, h67, l45, l67);                                     \
            uint32_t aoff = (uint32_t)((aRow + p * 32) * A_ROWB + aK8 * 2);     \
            sts4((sbuf) + ST_AH + aoff, h01, h23, h45, h67);                    \
            sts4((sbuf) + ST_AL + aoff, l01, l23, l45, l67);                    \
        }                                                                       \
        _Pragma("unroll")                                                       \
        for (int p = 0; p < 2; ++p) {                                           \
            int kk = bK + p * 16;                                               \
            const float* bp = B + (size_t)((k0) + kk) * NDIM + bn0 + bN8;       \
            float4 v0 = *(const float4*)bp;                                     \
            float4 v1 = *(const float4*)(bp + 4);                               \
            uint32_t h01, h23, l01, l23, h45, h67, l45, l67;                    \
            split4(v0, h01, h23, l01, l23);                                     \
            split4(v1, h45, h67, l45, l67);                                     \
            uint32_t boff = (uint32_t)(kk * 128 +                               \
                            ((bN8 * 2) ^ ((kk & 7) << 4)));                     \
            sts4((sbuf) + ST_BH + boff, h01, h23, h45, h67);                    \
            sts4((sbuf) + ST_BL + boff, l01, l23, l45, l67);                    \
        }                                                                       \
    }

    // prologue: fill stage 0
    PRODUCE_CHUNK(kStart, sbase);
    __syncthreads();

    for (int c = 0; c < nchunks; ++c) {
        const uint32_t scur = sbase + (uint32_t)(c & 1) * STAGE;

        // ---- compute on current stage ----
#pragma unroll
        for (int ks = 0; ks < BK; ks += 16) {
            uint32_t aH[4][4], aL[4][4], bH[2][4], bL[2][4];
#pragma unroll
            for (int mt = 0; mt < 4; ++mt) {
                uint32_t ar = scur + ST_AH +
                              (uint32_t)((m0w + 16 * mt) * A_ROWB + ks * 2) + laneA;
                ldm4(aH[mt], ar);
                ldm4(aL[mt], ar + (ST_AL - ST_AH));
            }
#pragma unroll
            for (int ntp = 0; ntp < 2; ++ntp) {
                uint32_t twoN0 = (uint32_t)((n0w + 16 * ntp) * 2);
                uint32_t br = scur + ST_BH + (uint32_t)(ks * 128) + laneBRow +
                              (twoN0 ^ laneBCol);
                ldm4t(bH[ntp], br);
                ldm4t(bL[ntp], br + (ST_BL - ST_BH));
            }
#pragma unroll
            for (int mt = 0; mt < 4; ++mt)
#pragma unroll
                for (int nt = 0; nt < 4; ++nt) {
                    const uint32_t* bh = &bH[nt >> 1][(nt & 1) * 2];
                    const uint32_t* bl = &bL[nt >> 1][(nt & 1) * 2];
                    mma16816(acc[mt][nt], aH[mt], bh);
                    mma16816(acc[mt][nt], aL[mt], bh);
                    mma16816(acc[mt][nt], aH[mt], bl);
                }
        }

        // ---- produce next stage (staging regs live only here) ----
        if (c + 1 < nchunks)
            PRODUCE_CHUNK(kStart + (c + 1) * BK,
                          sbase + (uint32_t)((c + 1) & 1) * STAGE);
        __syncthreads();
    }

    // ---- epilogue: tril-masked stores ----
#pragma unroll
    for (int mt = 0; mt < 4; ++mt) {
        const int r0 = bm0 + m0w + 16 * mt + (lane >> 2);
#pragma unroll
        for (int nt = 0; nt < 4; ++nt) {
            const int c0 = bn0 + n0w + 8 * nt + 2 * (lane & 3);
            float* p0 = C + (size_t)r0 * NDIM + c0;
            float* p1 = p0 + 8 * (size_t)NDIM;
            if (c0     <= r0)     p0[0] = acc[mt][nt][0];
            if (c0 + 1 <= r0)     p0[1] = acc[mt][nt][1];
            if (c0     <= r0 + 8) p1[0] = acc[mt][nt][2];
            if (c0 + 1 <= r0 + 8) p1[1] = acc[mt][nt][3];
        }
    }
}

extern "C" void kernel_launch(void* const* d_in, const int* in_sizes, int n_in,
                              void* d_out, int out_size) {
    const float* A = (const float*)d_in[0];
    const float* B = (const float*)d_in[1];
    float* C = (float*)d_out;

    cudaFuncSetAttribute(trimm_mma, cudaFuncAttributeMaxDynamicSharedMemorySize,
                         SMEM_DYN);

    // zero output (kernel never writes the strict upper triangle)
    cudaMemsetAsync(C, 0, (size_t)NDIM * NDIM * sizeof(float), 0);

    const int nblocks = NB * (NB + 1);   // 1056 half-tiles
    trimm_mma<<<nblocks, THREADS, SMEM_DYN>>>(A, B, C);
}

// round 7
// speedup vs baseline: 1.0121x; 1.0121x over previous
#include <cuda_runtime.h>
#include <cstdint>
#include <math.h>

// tril(A @ B), A,B lower-triangular fp32, N=4096.
// bf16 3-split GEMM on mma.sync.m16n8k16 (tcgen05/TMA unavailable: harness
// PTX target is sm_103 without 'a').
//
// R7: 128x128 C tiles (best L1-wavefronts/MMA = 1.67), 256 thr, 64x32 warp
// tiles, 2 CTAs/SM (launch_bounds(256,2), produce-after-compute to cap regs),
// split-K for the 136 largest-K tiles (seg1 -> static scratch, combine kernel
// adds back; deterministic, no atomics). 664 CTAs, max 64 chunk-units each.

#define NDIM 4096
#define NB   32
#define BK   32
#define THREADS 256

#define A_ROWB 80              // 32 bf16 = 64B padded to 80B (16B-divisible)
#define ST_AH 0                // 128*80 = 10240
#define ST_AL 10240
#define ST_BH 20480            // 32 k-rows * 256B = 8192
#define ST_BL 28672
#define STAGE 36864
#define SMEM_DYN (2 * STAGE)   // 73728/CTA; x2 = 147456

#define NSPLIT 136             // tiles t<136 have nc>=68 -> split in 2
__device__ float g_scratch[NSPLIT * 128 * 128];   // 8.9 MB static scratch

static __device__ __forceinline__ uint32_t smem_u32(const void* p) {
    uint32_t a;
    asm("{ .reg .u64 t; cvta.to.shared.u64 t, %1; cvt.u32.u64 %0, t; }"
        : "=r"(a) : "l"(p));
    return a;
}

// pack two fp32 -> bf16x2, 'lo' in bits[15:0], 'hi' in bits[31:16]
static __device__ __forceinline__ uint32_t bf2(float lo, float hi) {
    uint32_t r;
    asm("cvt.rn.bf16x2.f32 %0, %1, %2;" : "=r"(r) : "f"(hi), "f"(lo));
    return r;
}

static __device__ __forceinline__ void ldm4(uint32_t d[4], uint32_t addr) {
    asm volatile("ldmatrix.sync.aligned.m8n8.x4.shared.b16 {%0,%1,%2,%3}, [%4];"
                 : "=r"(d[0]), "=r"(d[1]), "=r"(d[2]), "=r"(d[3]) : "r"(addr));
}
static __device__ __forceinline__ void ldm4t(uint32_t d[4], uint32_t addr) {
    asm volatile("ldmatrix.sync.aligned.m8n8.x4.trans.shared.b16 {%0,%1,%2,%3}, [%4];"
                 : "=r"(d[0]), "=r"(d[1]), "=r"(d[2]), "=r"(d[3]) : "r"(addr));
}

static __device__ __forceinline__ void mma16816(float* c, const uint32_t* a,
                                                const uint32_t* b) {
    asm volatile(
        "mma.sync.aligned.m16n8k16.row.col.f32.bf16.bf16.f32 "
        "{%0,%1,%2,%3}, {%4,%5,%6,%7}, {%8,%9}, {%0,%1,%2,%3};"
        : "+f"(c[0]), "+f"(c[1]), "+f"(c[2]), "+f"(c[3])
        : "r"(a[0]), "r"(a[1]), "r"(a[2]), "r"(a[3]), "r"(b[0]), "r"(b[1]));
}

static __device__ __forceinline__ void split4(float4 v, uint32_t& h01, uint32_t& h23,
                                              uint32_t& l01, uint32_t& l23) {
    h01 = bf2(v.x, v.y);
    h23 = bf2(v.z, v.w);
    float r0 = v.x - __uint_as_float(h01 << 16);
    float r1 = v.y - __uint_as_float(h01 & 0xFFFF0000u);
    float r2 = v.z - __uint_as_float(h23 << 16);
    float r3 = v.w - __uint_as_float(h23 & 0xFFFF0000u);
    l01 = bf2(r0, r1);
    l23 = bf2(r2, r3);
}

static __device__ __forceinline__ void sts4(uint32_t addr, uint32_t a, uint32_t b,
                                            uint32_t c, uint32_t d) {
    asm volatile("st.shared.v4.b32 [%0], {%1,%2,%3,%4};"
                 :: "r"(addr), "r"(a), "r"(b), "r"(c), "r"(d) : "memory");
}

__global__ __launch_bounds__(THREADS, 2)
void trimm_mma(const float* __restrict__ A, const float* __restrict__ B,
               float* __restrict__ C)
{
    extern __shared__ __align__(128) char dyn_smem[];
    const uint32_t sbase = smem_u32(dyn_smem);

    const int tid  = threadIdx.x;
    const int wid  = tid >> 5;
    const int lane = tid & 31;

    // ---- block id -> (tile t, segment) ; split segments scheduled first ----
    const int bid = blockIdx.x;
    int t, seg;
    if (bid < 2 * NSPLIT) { t = bid >> 1; seg = bid & 1; }
    else                  { t = bid - 2 * NSPLIT + NSPLIT; seg = 0; }

    int g = (int)((sqrtf(8.0f * (float)t + 1.0f) - 1.0f) * 0.5f);
    while ((g + 1) * (g + 2) / 2 <= t) ++g;
    while (g * (g + 1) / 2 > t) --g;
    const int bj = t - g * (g + 1) / 2;
    const int bi = bj + (NB - 1) - g;
    const int bm0 = bi * 128, bn0 = bj * 128;

    const int nc = ((bm0 + 128) - bn0) >> 5;   // 4..128 chunk count
    const bool isSplit = (t < NSPLIT);         // nc >= 68 exactly when t<136
    const int cBeg = (isSplit && seg) ? (nc >> 1) : 0;
    const int cEndx = isSplit ? (seg ? nc : (nc >> 1)) : nc;

    // warp grid 2(m) x 4(n): warp tile 64x32
    const int m0w = (wid & 1) * 64;
    const int n0w = (wid >> 1) * 32;

    const uint32_t laneA    = (uint32_t)((lane & 15) * A_ROWB + ((lane >> 4) << 4));
    const uint32_t laneBRow = (uint32_t)((lane & 15) * 256);
    const uint32_t laneBCol = (uint32_t)((((lane >> 4) ^ (lane & 7)) << 4));

    // produce-phase indices: 8 floats/thread per pass, v4 stores
    const int aRow = tid >> 2;            // 0..63 (+64 second pass)
    const int aK8  = (tid & 3) * 8;       // k float offset {0,8,16,24}
    const int bK   = tid >> 4;            // 0..15 (+16 second pass)
    const int bN8  = (tid & 15) * 8;      // n float offset {0..120}

    float acc[4][4][4];
#pragma unroll
    for (int mt = 0; mt < 4; ++mt)
#pragma unroll
        for (int nt = 0; nt < 4; ++nt)
#pragma unroll
            for (int e = 0; e < 4; ++e) acc[mt][nt][e] = 0.0f;

#define PRODUCE(k0, sbuf)                                                       \
    {                                                                           \
        float4 va[4], vb[4];                                                    \
        const float* ap0 = A + (size_t)(bm0 + aRow) * NDIM + (k0) + aK8;        \
        const float* ap1 = A + (size_t)(bm0 + aRow + 64) * NDIM + (k0) + aK8;   \
        const float* bp0 = B + (size_t)((k0) + bK) * NDIM + bn0 + bN8;          \
        const float* bp1 = B + (size_t)((k0) + bK + 16) * NDIM + bn0 + bN8;     \
        va[0] = *(const float4*)ap0;  va[1] = *(const float4*)(ap0 + 4);        \
        va[2] = *(const float4*)ap1;  va[3] = *(const float4*)(ap1 + 4);        \
        vb[0] = *(const float4*)bp0;  vb[1] = *(const float4*)(bp0 + 4);        \
        vb[2] = *(const float4*)bp1;  vb[3] = *(const float4*)(bp1 + 4);        \
        _Pragma("unroll")                                                       \
        for (int p = 0; p < 2; ++p) {                                           \
            uint32_t h01, h23, l01, l23, h45, h67, l45, l67;                    \
            split4(va[2 * p], h01, h23, l01, l23);                              \
            split4(va[2 * p + 1], h45, h67, l45, l67);                          \
            uint32_t aoff = (uint32_t)((aRow + p * 64) * A_ROWB + aK8 * 2);     \
            sts4((sbuf) + ST_AH + aoff, h01, h23, h45, h67);                    \
            sts4((sbuf) + ST_AL + aoff, l01, l23, l45, l67);                    \
            split4(vb[2 * p], h01, h23, l01, l23);                              \
            split4(vb[2 * p + 1], h45, h67, l45, l67);                          \
            int kk = bK + p * 16;                                               \
            uint32_t boff = (uint32_t)(kk * 256 +                               \
                            ((bN8 * 2) ^ ((kk & 7) << 4)));                     \
            sts4((sbuf) + ST_BH + boff, h01, h23, h45, h67);                    \
            sts4((sbuf) + ST_BL + boff, l01, l23, l45, l67);                    \
        }                                                                       \
    }

    // prologue
    PRODUCE(bn0 + cBeg * BK, sbase);
    __syncthreads();

    for (int c = cBeg; c < cEndx; ++c) {
        const uint32_t scur = sbase + (uint32_t)((c - cBeg) & 1) * STAGE;

#pragma unroll
        for (int ks = 0; ks < BK; ks += 16) {
            uint32_t bH[2][4], bL[2][4];
#pragma unroll
            for (int ntp = 0; ntp < 2; ++ntp) {
                uint32_t twoN0 = (uint32_t)((n0w + 16 * ntp) * 2);
                uint32_t br = scur + ST_BH + (uint32_t)(ks * 256) + laneBRow +
                              (twoN0 ^ laneBCol);
                ldm4t(bH[ntp], br);
                ldm4t(bL[ntp], br + (ST_BL - ST_BH));
            }
            // a-fragments double-buffered across mt
            uint32_t aH[2][4], aL[2][4];
            {
                uint32_t ar = scur + ST_AH + (uint32_t)(m0w * A_ROWB + ks * 2) + laneA;
                ldm4(aH[0], ar);
                ldm4(aL[0], ar + (ST_AL - ST_AH));
            }
#pragma unroll
            for (int mt = 0; mt < 4; ++mt) {
                const int cur = mt & 1;
                if (mt < 3) {
                    uint32_t ar = scur + ST_AH +
                                  (uint32_t)((m0w + 16 * (mt + 1)) * A_ROWB + ks * 2) + laneA;
                    ldm4(aH[cur ^ 1], ar);
                    ldm4(aL[cur ^ 1], ar + (ST_AL - ST_AH));
                }
#pragma unroll
                for (int nt = 0; nt < 4; ++nt) {
                    const uint32_t* bh = &bH[nt >> 1][(nt & 1) * 2];
                    const uint32_t* bl = &bL[nt >> 1][(nt & 1) * 2];
                    mma16816(acc[mt][nt], aH[cur], bh);
                    mma16816(acc[mt][nt], aL[cur], bh);
                    mma16816(acc[mt][nt], aH[cur], bl);
                }
            }
        }

        if (c + 1 < cEndx)
            PRODUCE(bn0 + (c + 1) * BK,
                    sbase + (uint32_t)((c + 1 - cBeg) & 1) * STAGE);
        __syncthreads();
    }

    // ---- epilogue ----
    if (isSplit && seg) {
        // partial -> scratch (split tiles are strictly below diagonal; no mask)
        float* S = g_scratch + (size_t)t * 16384;
#pragma unroll
        for (int mt = 0; mt < 4; ++mt) {
            const int rl = m0w + 16 * mt + (lane >> 2);
#pragma unroll
            for (int nt = 0; nt < 4; ++nt) {
                const int cl = n0w + 8 * nt + 2 * (lane & 3);
                S[rl * 128 + cl]           = acc[mt][nt][0];
                S[rl * 128 + cl + 1]       = acc[mt][nt][1];
                S[(rl + 8) * 128 + cl]     = acc[mt][nt][2];
                S[(rl + 8) * 128 + cl + 1] = acc[mt][nt][3];
            }
        }
    } else {
#pragma unroll
        for (int mt = 0; mt < 4; ++mt) {
            const int r0 = bm0 + m0w + 16 * mt + (lane >> 2);
#pragma unroll
            for (int nt = 0; nt < 4; ++nt) {
                const int c0 = bn0 + n0w + 8 * nt + 2 * (lane & 3);
                float* p0 = C + (size_t)r0 * NDIM + c0;
                float* p1 = p0 + 8 * (size_t)NDIM;
                if (c0     <= r0)     p0[0] = acc[mt][nt][0];
                if (c0 + 1 <= r0)     p0[1] = acc[mt][nt][1];
                if (c0     <= r0 + 8) p1[0] = acc[mt][nt][2];
                if (c0 + 1 <= r0 + 8) p1[1] = acc[mt][nt][3];
            }
        }
    }
}

// add seg1 partials into C (split tiles only; all strictly lower-triangular)
__global__ __launch_bounds__(256)
void combine_scratch(float* __restrict__ C)
{
    const int idx = blockIdx.x * 256 + threadIdx.x;   // < NSPLIT*16384
    const int t   = idx >> 14;
    const int loc = idx & 16383;
    int g = (int)((sqrtf(8.0f * (float)t + 1.0f) - 1.0f) * 0.5f);
    while ((g + 1) * (g + 2) / 2 <= t) ++g;
    while (g * (g + 1) / 2 > t) --g;
    const int bj = t - g * (g + 1) / 2;
    const int bi = bj + (NB - 1) - g;
    const int r = bi * 128 + (loc >> 7);
    const int c = bj * 128 + (loc & 127);
    C[(size_t)r * NDIM + c] += g_scratch[idx];
}

extern "C" void kernel_launch(void* const* d_in, const int* in_sizes, int n_in,
                              void* d_out, int out_size) {
    const float* A = (const float*)d_in[0];
    const float* B = (const float*)d_in[1];
    float* C = (float*)d_out;

    cudaFuncSetAttribute(trimm_mma, cudaFuncAttributeMaxDynamicSharedMemorySize,
                         SMEM_DYN);

    cudaMemsetAsync(C, 0, (size_t)NDIM * NDIM * sizeof(float), 0);

    const int nblocks = 2 * NSPLIT + (NB * (NB + 1) / 2 - NSPLIT);   // 664
    trimm_mma<<<nblocks, THREADS, SMEM_DYN>>>(A, B, C);
    combine_scratch<<<NSPLIT * 16384 / 256, 256>>>(C);
}